// round 2
// baseline (speedup 1.0000x reference)
#include <cuda_runtime.h>

typedef unsigned long long u64;

#define D_F 16
#define HID 16

// ---- f32x2 packed helpers (Blackwell FFMA2 path) ----
__device__ __forceinline__ u64 ffma2(u64 a, u64 b, u64 c) {
    u64 r;
    asm("fma.rn.f32x2 %0, %1, %2, %3;" : "=l"(r) : "l"(a), "l"(b), "l"(c));
    return r;
}
__device__ __forceinline__ u64 pack2(float v) {
    u64 r; unsigned i = __float_as_uint(v);
    asm("mov.b64 %0, {%1, %1};" : "=l"(r) : "r"(i));
    return r;
}
__device__ __forceinline__ u64 pack2f(float lo, float hi) {
    u64 r;
    asm("mov.b64 %0, {%1, %2};" : "=l"(r)
        : "r"(__float_as_uint(lo)), "r"(__float_as_uint(hi)));
    return r;
}
__device__ __forceinline__ u64 relu2(u64 v) {
    unsigned lo, hi;
    asm("mov.b64 {%0, %1}, %2;" : "=r"(lo), "=r"(hi) : "l"(v));
    float flo = fmaxf(__uint_as_float(lo), 0.0f);
    float fhi = fmaxf(__uint_as_float(hi), 0.0f);
    return pack2f(flo, fhi);
}
__device__ __forceinline__ float lo_of(u64 v) {
    unsigned lo, hi;
    asm("mov.b64 {%0, %1}, %2;" : "=r"(lo), "=r"(hi) : "l"(v));
    return __uint_as_float(lo);
}

// Shared layouts (all weights duplicated as (w,w) f32x2 payloads):
//   sW1[d][c][h]  : 16*3*16  u64  (6144 B)  - layer1, vectorizable over h
//   sW2[d][g][h]  : 16*16*16 u64  (32768 B) - layer2 rows
//   sW3[d][g][o]  : 16*16*3  u64  (6144 B)  - layer3 TRANSPOSED for fusion
//   sB2[d][g]     : 256      u64  (2048 B)  - dup bias, direct LDS.64 accum init
//   sB1, sB3      : f32 (1024 + 192 B)
// Total = 48320 B  (< 48 KB static limit; 4 blocks/SM = 193 KB)

__global__ __launch_bounds__(128, 4)
void fields_kernel(const float* __restrict__ x,
                   const float* __restrict__ W1, const float* __restrict__ b1,
                   const float* __restrict__ W2, const float* __restrict__ b2,
                   const float* __restrict__ W3, const float* __restrict__ b3,
                   float* __restrict__ out, int N)
{
    __shared__ __align__(16) u64 sW1[D_F * 3 * HID];
    __shared__ __align__(16) u64 sW2[D_F * HID * HID];
    __shared__ __align__(16) u64 sW3[D_F * HID * 3];
    __shared__ __align__(16) u64 sB2[D_F * HID];
    __shared__ float sB1[D_F * HID];
    __shared__ float sB3[D_F * 3];

    const int tid = threadIdx.x;
    // sW1[d][c][h] <- W1[d][h][c]
    for (int i = tid; i < D_F * 3 * HID; i += blockDim.x) {
        int d = i / 48, rem = i % 48, c = rem / HID, h = rem % HID;
        sW1[i] = pack2(W1[d * 48 + h * 3 + c]);
    }
    for (int i = tid; i < D_F * HID * HID; i += blockDim.x) sW2[i] = pack2(W2[i]);
    // sW3[d][g][o] <- W3[d][o][g]
    for (int i = tid; i < D_F * HID * 3; i += blockDim.x) {
        int d = i / 48, rem = i % 48, g = rem / 3, o = rem % 3;
        sW3[i] = pack2(W3[d * 48 + o * HID + g]);
    }
    for (int i = tid; i < D_F * HID; i += blockDim.x) { sB2[i] = pack2(b2[i]); sB1[i] = b1[i]; }
    for (int i = tid; i < D_F * 3;   i += blockDim.x) sB3[i] = b3[i];
    __syncthreads();

    const int q    = blockIdx.x * blockDim.x + tid;
    const int base = q * 4;

    if (base + 3 < N) {
        // 4 points per thread: two f32x2 pairs (A = pts 0,1 ; B = pts 2,3)
        u64 xA[3], xB[3];
        #pragma unroll
        for (int c = 0; c < 3; c++) {
            ulonglong2 v = *reinterpret_cast<const ulonglong2*>(x + (size_t)c * N + base);
            xA[c] = v.x; xB[c] = v.y;
        }

        #pragma unroll 1
        for (int d = 0; d < D_F; d++) {
            // ---- layer 1: h1 = relu(W1 @ x + b1) ----
            u64 h1A[HID], h1B[HID];
            {
                const float* bb1 = sB1 + d * HID;
                #pragma unroll
                for (int h = 0; h < HID; h++) {
                    u64 bb = pack2(bb1[h]);
                    h1A[h] = bb; h1B[h] = bb;
                }
                #pragma unroll
                for (int c = 0; c < 3; c++) {
                    const ulonglong2* wc =
                        reinterpret_cast<const ulonglong2*>(sW1 + (d * 3 + c) * HID);
                    u64 xa = xA[c], xb = xB[c];
                    #pragma unroll
                    for (int hp = 0; hp < HID / 2; hp++) {
                        ulonglong2 w = wc[hp];  // LDS.128: two dup weights
                        h1A[2*hp]   = ffma2(w.x, xa, h1A[2*hp]);
                        h1B[2*hp]   = ffma2(w.x, xb, h1B[2*hp]);
                        h1A[2*hp+1] = ffma2(w.y, xa, h1A[2*hp+1]);
                        h1B[2*hp+1] = ffma2(w.y, xb, h1B[2*hp+1]);
                    }
                }
                #pragma unroll
                for (int h = 0; h < HID; h++) {
                    h1A[h] = relu2(h1A[h]); h1B[h] = relu2(h1B[h]);
                }
            }

            // ---- layers 2+3 fused: out_o = b3_o + sum_g W3[o][g]*relu(W2[g]@h1+b2[g]) ----
            u64 oA[3], oB[3];
            #pragma unroll
            for (int o = 0; o < 3; o++) {
                u64 t = pack2(sB3[d * 3 + o]);
                oA[o] = t; oB[o] = t;
            }

            #pragma unroll
            for (int g = 0; g < HID; g++) {
                u64 a = sB2[d * HID + g];  // LDS.64 pre-dup'd bias
                u64 b = a;
                const ulonglong2* wr =
                    reinterpret_cast<const ulonglong2*>(sW2 + (d * HID + g) * HID);
                #pragma unroll
                for (int hp = 0; hp < HID / 2; hp++) {
                    ulonglong2 w = wr[hp];  // LDS.128
                    a = ffma2(w.x, h1A[2*hp],   a);  b = ffma2(w.x, h1B[2*hp],   b);
                    a = ffma2(w.y, h1A[2*hp+1], a);  b = ffma2(w.y, h1B[2*hp+1], b);
                }
                a = relu2(a); b = relu2(b);

                const u64* w3 = sW3 + (d * HID + g) * 3;
                #pragma unroll
                for (int o = 0; o < 3; o++) {
                    u64 w = w3[o];
                    oA[o] = ffma2(w, a, oA[o]);
                    oB[o] = ffma2(w, b, oB[o]);
                }
            }

            #pragma unroll
            for (int o = 0; o < 3; o++) {
                *reinterpret_cast<ulonglong2*>(out + (size_t)(d * 3 + o) * N + base) =
                    make_ulonglong2(oA[o], oB[o]);
            }
        }
    } else {
        // scalar tail (unused when N % 4 == 0)
        for (int p = base; p < N && p >= 0; p++) {
            float xs[3];
            #pragma unroll
            for (int c = 0; c < 3; c++) xs[c] = x[(size_t)c * N + p];
            for (int d = 0; d < D_F; d++) {
                float h1[HID];
                for (int h = 0; h < HID; h++) {
                    float s = sB1[d * HID + h];
                    for (int c = 0; c < 3; c++)
                        s += lo_of(sW1[(d * 3 + c) * HID + h]) * xs[c];
                    h1[h] = fmaxf(s, 0.0f);
                }
                float o0 = sB3[d*3+0], o1 = sB3[d*3+1], o2 = sB3[d*3+2];
                for (int g = 0; g < HID; g++) {
                    float s = lo_of(sB2[d * HID + g]);
                    for (int h = 0; h < HID; h++)
                        s += lo_of(sW2[(d * HID + g) * HID + h]) * h1[h];
                    s = fmaxf(s, 0.0f);
                    o0 += lo_of(sW3[(d * HID + g) * 3 + 0]) * s;
                    o1 += lo_of(sW3[(d * HID + g) * 3 + 1]) * s;
                    o2 += lo_of(sW3[(d * HID + g) * 3 + 2]) * s;
                }
                out[(size_t)(d * 3 + 0) * N + p] = o0;
                out[(size_t)(d * 3 + 1) * N + p] = o1;
                out[(size_t)(d * 3 + 2) * N + p] = o2;
            }
        }
    }
}

extern "C" void kernel_launch(void* const* d_in, const int* in_sizes, int n_in,
                              void* d_out, int out_size)
{
    const float* x  = (const float*)d_in[0];
    const float* W1 = (const float*)d_in[1];
    const float* b1 = (const float*)d_in[2];
    const float* W2 = (const float*)d_in[3];
    const float* b2 = (const float*)d_in[4];
    const float* W3 = (const float*)d_in[5];
    const float* b3 = (const float*)d_in[6];
    float* out = (float*)d_out;

    const int N  = in_sizes[0] / 3;        // x is [1,3,N]
    const int nq = (N + 3) / 4;            // 4 points per thread
    const int grid = (nq + 127) / 128;

    fields_kernel<<<grid, 128>>>(x, W1, b1, W2, b2, W3, b3, out, N);
}